// round 3
// baseline (speedup 1.0000x reference)
#include <cuda_runtime.h>
#include <cuda_bf16.h>

// Sparsemax along last dim, rows of N=2048 fp32.
//
// tau in [M-1, M)  (M = row max), so support is a subset of {x > M-1}
// (~4-10 elements for Gaussian rows). Per row:
//   pass1: row max M (block reduce)
//   pass2: compact {x > M-1} to shared + (S,C); tau1=(S-1)/C
//   warp 0: Newton fixed point on the tiny candidate list
//   output relu(x - tau) from registers.
//
// R3: persistent grid-stride blocks (no wave transitions) + prefetch of the
// next row's loads before the current row's barriers/Newton, so DRAM traffic
// never drains. Streaming cache hints (touch-once data).

constexpr int ROW_N   = 2048;
constexpr int THREADS = 256;
constexpr int VPT     = ROW_N / THREADS;   // 8
constexpr int NWARP   = THREADS / 32;      // 8
constexpr int ROW_F4  = ROW_N / 4;         // 512 float4 per row

__global__ __launch_bounds__(THREADS, 6)
void sparsemax_kernel(const float* __restrict__ in, float* __restrict__ out,
                      int rows) {
    __shared__ float list[ROW_N];
    __shared__ float pm[NWARP];
    __shared__ float ps[NWARP];
    __shared__ float pc[NWARP];
    __shared__ int   scount;
    __shared__ float stau;

    const int t    = threadIdx.x;
    const int lane = t & 31;
    const int warp = t >> 5;
    const int stride = gridDim.x;

    int row = blockIdx.x;
    if (row >= rows) return;

    const float4* x4 = (const float4*)in;
    float4*       y4 = (float4*)out;

    size_t rb = (size_t)row * ROW_F4;
    float4 a0 = __ldcs(&x4[rb + t]);
    float4 a1 = __ldcs(&x4[rb + t + THREADS]);

    for (;;) {
        // ---- prefetch next row (overlaps everything below) ----
        const int nrow = row + stride;
        const bool have_next = nrow < rows;
        float4 b0, b1;
        if (have_next) {
            size_t nb = (size_t)nrow * ROW_F4;
            b0 = __ldcs(&x4[nb + t]);
            b1 = __ldcs(&x4[nb + t + THREADS]);
        }

        float v[VPT] = {a0.x, a0.y, a0.z, a0.w, a1.x, a1.y, a1.z, a1.w};

        // ---- pass 1: row max ----
        float m = v[0];
#pragma unroll
        for (int j = 1; j < VPT; j++) m = fmaxf(m, v[j]);
#pragma unroll
        for (int o = 16; o; o >>= 1)
            m = fmaxf(m, __shfl_xor_sync(0xffffffffu, m, o));
        if (lane == 0) pm[warp] = m;
        if (t == 0) scount = 0;
        __syncthreads();                               // bar 1

        float M = pm[0];
#pragma unroll
        for (int w = 1; w < NWARP; w++) M = fmaxf(M, pm[w]);
        const float thr = M - 1.0f;

        // ---- pass 2: compact candidates {x > M-1}, accumulate (S, C) ----
        float s = 0.f, c = 0.f;
        float loc[VPT];
        int nloc = 0;
#pragma unroll
        for (int j = 0; j < VPT; j++) {
            if (v[j] > thr) { s += v[j]; c += 1.0f; loc[nloc++] = v[j]; }
        }
        if (nloc) {                                    // rare per thread
            int base = atomicAdd(&scount, nloc);
            for (int i = 0; i < nloc; i++) list[base + i] = loc[i];
        }
#pragma unroll
        for (int o = 16; o; o >>= 1) {
            s += __shfl_down_sync(0xffffffffu, s, o);
            c += __shfl_down_sync(0xffffffffu, c, o);
        }
        if (lane == 0) { ps[warp] = s; pc[warp] = c; }
        __syncthreads();                               // bar 2

        // ---- warp 0: Newton fixed point on the candidate list ----
        if (warp == 0) {
            float S = ps[0], C = pc[0];
#pragma unroll
            for (int w = 1; w < NWARP; w++) { S += ps[w]; C += pc[w]; }
            const int cnt = scount;                    // == (int)C
            float tau = (S - 1.0f) / C;
            int kprev = cnt;

            for (int iter = 0; iter < 64; ++iter) {
                float s2 = 0.f, c2 = 0.f;
                for (int k = lane; k < cnt; k += 32) {
                    float w = list[k];
                    if (w > tau) { s2 += w; c2 += 1.0f; }
                }
#pragma unroll
                for (int o = 16; o; o >>= 1) {
                    s2 += __shfl_xor_sync(0xffffffffu, s2, o);
                    c2 += __shfl_xor_sync(0xffffffffu, c2, o);
                }
                int k2 = (int)c2;                      // max always survives
                tau = (s2 - 1.0f) / c2;
                if (k2 == kprev) break;                // support stable
                kprev = k2;
            }
            if (lane == 0) stau = tau;
        }
        __syncthreads();                               // bar 3

        // ---- output: relu(x - tau) from preserved registers ----
        const float tau = stau;
        float4 o0, o1;
        o0.x = fmaxf(v[0] - tau, 0.f);
        o0.y = fmaxf(v[1] - tau, 0.f);
        o0.z = fmaxf(v[2] - tau, 0.f);
        o0.w = fmaxf(v[3] - tau, 0.f);
        o1.x = fmaxf(v[4] - tau, 0.f);
        o1.y = fmaxf(v[5] - tau, 0.f);
        o1.z = fmaxf(v[6] - tau, 0.f);
        o1.w = fmaxf(v[7] - tau, 0.f);

        size_t ob = (size_t)row * ROW_F4;
        __stcs(&y4[ob + t],           o0);
        __stcs(&y4[ob + t + THREADS], o1);

        if (!have_next) break;
        row = nrow;
        a0 = b0;
        a1 = b1;
    }
}

extern "C" void kernel_launch(void* const* d_in, const int* in_sizes, int n_in,
                              void* d_out, int out_size) {
    const float* in = (const float*)d_in[0];
    float* out = (float*)d_out;
    int rows = in_sizes[0] / ROW_N;      // 2*16*2048 = 65536
    int grid = 148 * 6;                  // persistent: fills 148 SMs at 6 blocks/SM
    if (grid > rows) grid = rows;
    sparsemax_kernel<<<grid, THREADS>>>(in, out, rows);
}

// round 4
// speedup vs baseline: 1.4463x; 1.4463x over previous
#include <cuda_runtime.h>
#include <cuda_bf16.h>

// Sparsemax along last dim, rows of N=2048 fp32.
//
// tau in [M-1, M)  (M = row max)  =>  support ⊆ {x > M-1} (~7 of 2048 for
// Gaussian rows). R4: ONE WARP PER ROW, row in registers (64 vals/lane,
// 16x LDG.128 front-batched). No shared memory, no barriers, no atomics:
//   - warp max via shfl
//   - per-lane top-4 candidates above M-1 kept in 4 registers via a
//     predicated sorted insert (no dynamic indexing)
//   - Newton fixed point tau <- (sum_{x>tau} - 1)/count, shfl reductions,
//     terminates exactly when the support count is stable
//   - fallback (warp-uniform) full re-scan path if any lane holds >4
//     candidates (degenerate inputs only; still exact)
//   - output relu(x - tau) from registers.

constexpr int ROW_N   = 2048;
constexpr int WARPS_B = 4;
constexpr int THREADS = 32 * WARPS_B;   // 128
constexpr int F4PT    = ROW_N / 4 / 32; // 16 float4 per lane

__global__ __launch_bounds__(THREADS)
void sparsemax_kernel(const float* __restrict__ in, float* __restrict__ out,
                      int rows) {
    const int lane = threadIdx.x & 31;
    const int row  = blockIdx.x * WARPS_B + (threadIdx.x >> 5);
    if (row >= rows) return;

    const float4* x4 = (const float4*)(in  + (size_t)row * ROW_N);
    float4*       y4 = (float4*)      (out + (size_t)row * ROW_N);

    // ---- load row: 16 coalesced LDG.128 per lane (batched -> high MLP) ----
    float4 a[F4PT];
#pragma unroll
    for (int i = 0; i < F4PT; i++) a[i] = __ldcs(&x4[lane + 32 * i]);

    // ---- row max ----
    float m = fmaxf(fmaxf(a[0].x, a[0].y), fmaxf(a[0].z, a[0].w));
#pragma unroll
    for (int i = 1; i < F4PT; i++) {
        float mi = fmaxf(fmaxf(a[i].x, a[i].y), fmaxf(a[i].z, a[i].w));
        m = fmaxf(m, mi);
    }
#pragma unroll
    for (int o = 16; o; o >>= 1)
        m = fmaxf(m, __shfl_xor_sync(0xffffffffu, m, o));
    const float thr = m - 1.0f;

    // ---- candidates {x > M-1}: per-lane top-4 in registers + (sum,count) ----
    const float NEG = -3.0e38f;
    float c0 = NEG, c1 = NEG, c2 = NEG, c3 = NEG;
    float ss = 0.f;
    int   nc = 0;
#pragma unroll
    for (int i = 0; i < F4PT; i++) {
        float e[4] = {a[i].x, a[i].y, a[i].z, a[i].w};
#pragma unroll
        for (int j = 0; j < 4; j++) {
            float x = e[j];
            if (x > thr) {                 // rare (expected ~0.2 per lane)
                ss += x; nc++;
                float r0 = fminf(c0, x); c0 = fmaxf(c0, x);
                float r1 = fminf(c1, r0); c1 = fmaxf(c1, r0);
                float r2 = fminf(c2, r1); c2 = fmaxf(c2, r1);
                c3 = fmaxf(c3, r2);
            }
        }
    }

    // warp reductions: sum, count, max per-lane count
    float cc = (float)nc;
    int ncmax = nc;
#pragma unroll
    for (int o = 16; o; o >>= 1) {
        ss += __shfl_xor_sync(0xffffffffu, ss, o);
        cc += __shfl_xor_sync(0xffffffffu, cc, o);
        ncmax = max(ncmax, __shfl_xor_sync(0xffffffffu, ncmax, o));
    }

    float tau = (ss - 1.0f) / cc;          // Newton step from thr; tau >= thr
    int kprev = (int)cc;

    if (ncmax <= 4) {
        // ---- fast path: Newton over the register-resident top-4 lists ----
        for (int iter = 0; iter < 40; ++iter) {
            float s2 = 0.f, c2f = 0.f;
            if (c0 > tau) { s2 += c0; c2f += 1.f; }
            if (c1 > tau) { s2 += c1; c2f += 1.f; }
            if (c2 > tau) { s2 += c2; c2f += 1.f; }
            if (c3 > tau) { s2 += c3; c2f += 1.f; }
#pragma unroll
            for (int o = 16; o; o >>= 1) {
                s2  += __shfl_xor_sync(0xffffffffu, s2, o);
                c2f += __shfl_xor_sync(0xffffffffu, c2f, o);
            }
            int k2 = (int)c2f;             // max element always survives
            tau = (s2 - 1.0f) / c2f;
            if (k2 == kprev) break;        // support stable -> exact
            kprev = k2;
        }
    } else {
        // ---- fallback (degenerate rows): re-scan all 64 values per iter ----
        for (int iter = 0; iter < 64; ++iter) {
            float s2 = 0.f, c2f = 0.f;
#pragma unroll
            for (int i = 0; i < F4PT; i++) {
                if (a[i].x > tau) { s2 += a[i].x; c2f += 1.f; }
                if (a[i].y > tau) { s2 += a[i].y; c2f += 1.f; }
                if (a[i].z > tau) { s2 += a[i].z; c2f += 1.f; }
                if (a[i].w > tau) { s2 += a[i].w; c2f += 1.f; }
            }
#pragma unroll
            for (int o = 16; o; o >>= 1) {
                s2  += __shfl_xor_sync(0xffffffffu, s2, o);
                c2f += __shfl_xor_sync(0xffffffffu, c2f, o);
            }
            int k2 = (int)c2f;
            tau = (s2 - 1.0f) / c2f;
            if (k2 == kprev) break;
            kprev = k2;
        }
    }

    // ---- output: relu(x - tau) from registers, 16 STG.128 ----
#pragma unroll
    for (int i = 0; i < F4PT; i++) {
        float4 o;
        o.x = fmaxf(a[i].x - tau, 0.f);
        o.y = fmaxf(a[i].y - tau, 0.f);
        o.z = fmaxf(a[i].z - tau, 0.f);
        o.w = fmaxf(a[i].w - tau, 0.f);
        __stcs(&y4[lane + 32 * i], o);
    }
}

extern "C" void kernel_launch(void* const* d_in, const int* in_sizes, int n_in,
                              void* d_out, int out_size) {
    const float* in = (const float*)d_in[0];
    float* out = (float*)d_out;
    int rows = in_sizes[0] / ROW_N;              // 65536
    int grid = (rows + WARPS_B - 1) / WARPS_B;   // 16384 blocks of 128
    sparsemax_kernel<<<grid, THREADS>>>(in, out, rows);
}